// round 7
// baseline (speedup 1.0000x reference)
#include <cuda_runtime.h>

// Problem geometry
#define IMG_H 512
#define IMG_W 512
#define NBATCH 32
#define CH_STRIDE (NBATCH * IMG_H * IMG_W)   // per-channel stride (elements)
#define B_STRIDE  (IMG_H * IMG_W)            // per-batch stride

// Tile geometry: 64 wide x 16 high output tile, +1 halo each side.
#define TW 64
#define TH 16
#define TROWS (TH + 2)      // 18
#define TCOLS (TW + 2)      // 66 valid columns
#define PITCH 68            // padded so row starts are 16B-aligned for float4 LDS
#define FELEMS (TROWS * PITCH)  // 1224 floats per field
#define NF 10               // s0..s3, f0..f5
#define SMEM_FLOATS (NF * FELEMS)   // 12240 floats = 48960 B (static, <48KB limit)

__constant__ float cw[108];   // 12 3x3 kernels

// cbrt via MUFU lg2/ex2: x >= 0 always here (uniform [0,1) inputs).
// x==0: lg2 -> -inf, ex2(-inf) -> 0. Rel err ~1e-6, fine for 1e-3 gate.
__device__ __forceinline__ float cbrt_fast(float x) {
    float lg;
    asm("lg2.approx.f32 %0, %1;" : "=f"(lg) : "f"(x));
    float e = lg * 0.33333333333333f;
    float r;
    asm("ex2.approx.f32 %0, %1;" : "=f"(r) : "f"(e));
    return r;
}

__device__ __forceinline__ void ldrow(const float* __restrict__ row, float v[6]) {
    float4 a  = *reinterpret_cast<const float4*>(row);      // 16B aligned
    float2 bb = *reinterpret_cast<const float2*>(row + 4);  // 8B aligned
    v[0] = a.x; v[1] = a.y; v[2] = a.z; v[3] = a.w; v[4] = bb.x; v[5] = bb.y;
}

// 3x3 conv over a 4-wide x 2-HIGH output block, one weight set.
// Window = 4 rows x 6 cols starting at t+off. Output row oy uses window rows
// oy..oy+2. Rows 1 and 2 are the center rows -> optionally captured to cen.
__device__ __forceinline__ void conv1h(const float* __restrict__ t, int off, int wb,
                                       float acc[2][4], float (*cen)[4]) {
    #pragma unroll
    for (int r = 0; r < 4; r++) {
        float v[6];
        ldrow(t + off + r * PITCH, v);
        if (cen && (r == 1 || r == 2)) {
            float* c = cen[r - 1];
            c[0] = v[1]; c[1] = v[2]; c[2] = v[3]; c[3] = v[4];
        }
        #pragma unroll
        for (int oy = 0; oy < 2; oy++) {
            const int dy = r - oy;
            if (dy >= 0 && dy < 3) {
                #pragma unroll
                for (int ox = 0; ox < 4; ox++) {
                    acc[oy][ox] = fmaf(cw[wb + dy * 3 + 0], v[ox + 0], acc[oy][ox]);
                    acc[oy][ox] = fmaf(cw[wb + dy * 3 + 1], v[ox + 1], acc[oy][ox]);
                    acc[oy][ox] = fmaf(cw[wb + dy * 3 + 2], v[ox + 2], acc[oy][ox]);
                }
            }
        }
    }
}

// Same window, two (weight, accumulator) pairs — shares the row loads.
__device__ __forceinline__ void conv2h(const float* __restrict__ t, int off,
                                       int wbA, float accA[2][4],
                                       int wbB, float accB[2][4], float (*cen)[4]) {
    #pragma unroll
    for (int r = 0; r < 4; r++) {
        float v[6];
        ldrow(t + off + r * PITCH, v);
        if (cen && (r == 1 || r == 2)) {
            float* c = cen[r - 1];
            c[0] = v[1]; c[1] = v[2]; c[2] = v[3]; c[3] = v[4];
        }
        #pragma unroll
        for (int oy = 0; oy < 2; oy++) {
            const int dy = r - oy;
            if (dy >= 0 && dy < 3) {
                #pragma unroll
                for (int ox = 0; ox < 4; ox++) {
                    accA[oy][ox] = fmaf(cw[wbA + dy * 3 + 0], v[ox + 0], accA[oy][ox]);
                    accA[oy][ox] = fmaf(cw[wbA + dy * 3 + 1], v[ox + 1], accA[oy][ox]);
                    accA[oy][ox] = fmaf(cw[wbA + dy * 3 + 2], v[ox + 2], accA[oy][ox]);
                    accB[oy][ox] = fmaf(cw[wbB + dy * 3 + 0], v[ox + 0], accB[oy][ox]);
                    accB[oy][ox] = fmaf(cw[wbB + dy * 3 + 1], v[ox + 1], accB[oy][ox]);
                    accB[oy][ox] = fmaf(cw[wbB + dy * 3 + 2], v[ox + 2], accB[oy][ox]);
                }
            }
        }
    }
}

__device__ __forceinline__ void store8(float* p, const float cen[2][4],
                                       const float acc[2][4]) {
    #pragma unroll
    for (int oy = 0; oy < 2; oy++) {
        float4 v = { cen[oy][0] - acc[oy][0], cen[oy][1] - acc[oy][1],
                     cen[oy][2] - acc[oy][2], cen[oy][3] - acc[oy][3] };
        *reinterpret_cast<float4*>(p + oy * IMG_W) = v;
    }
}

__global__ __launch_bounds__(128, 4)
void fused_bleed(const float* __restrict__ src, float* __restrict__ out) {
    __shared__ float sm[SMEM_FLOATS];

    const int tid = threadIdx.x;
    const int x0 = blockIdx.x * TW;
    const int y0 = blockIdx.y * TH;
    const int b  = blockIdx.z;

    const float* base = src + b * B_STRIDE;

    // ---- Load halo tiles for all 4 channels; compute the 6 inter fields inline.
    // inter(i,j) = (s_j^0.5 * s_i)^(2/3) = cbrt(s_j) * cbrt(s_i)^2
    for (int idx = tid; idx < TROWS * TCOLS; idx += 128) {
        const int ly = idx / TCOLS;
        const int lx = idx - ly * TCOLS;
        const int gy = y0 - 1 + ly;
        const int gx = x0 - 1 + lx;
        float s0 = 0.f, s1 = 0.f, s2 = 0.f, s3 = 0.f;
        if ((unsigned)gy < (unsigned)IMG_H && (unsigned)gx < (unsigned)IMG_W) {
            const int g = gy * IMG_W + gx;
            s0 = base[g];
            s1 = base[g + CH_STRIDE];
            s2 = base[g + 2 * CH_STRIDE];
            s3 = base[g + 3 * CH_STRIDE];
        }
        const int o = ly * PITCH + lx;
        sm[o]              = s0;
        sm[o + FELEMS]     = s1;
        sm[o + 2 * FELEMS] = s2;
        sm[o + 3 * FELEMS] = s3;
        const float c0 = cbrt_fast(s0), c1 = cbrt_fast(s1);
        const float c2 = cbrt_fast(s2), c3 = cbrt_fast(s3);
        const float q0 = c0 * c0, q1 = c1 * c1, q2 = c2 * c2, q3 = c3 * c3;
        sm[o + 4 * FELEMS] = c1 * q0;   // f0: (i=0,j=1) -> K1
        sm[o + 5 * FELEMS] = c0 * q1;   // f1: (1,0) -> K3
        sm[o + 6 * FELEMS] = c2 * q1;   // f2: (1,2) -> K5
        sm[o + 7 * FELEMS] = c1 * q2;   // f3: (2,1) -> K7
        sm[o + 8 * FELEMS] = c3 * q2;   // f4: (2,3) -> K9
        sm[o + 9 * FELEMS] = c2 * q3;   // f5: (3,2) -> K11
    }
    __syncthreads();

    // ---- Compute phase: each thread owns a 4-wide x 2-HIGH block, all 4 channels.
    const int tx = tid & 15;            // 0..15 -> column block
    const int ty = tid >> 4;            // 0..7  -> output row pair
    const int off = (2 * ty) * PITCH + tx * 4;   // window top-left in smem
    float* outp = out + b * B_STRIDE + (y0 + 2 * ty) * IMG_W + (x0 + tx * 4);

    float acc0[2][4] = {}, acc1[2][4] = {}, acc2[2][4] = {}, acc3[2][4] = {};
    float cen0[2][4], cen1[2][4], cen2[2][4], cen3[2][4];

    // s0: feeds out1 (K2); centers for out0.
    conv1h(sm + 0 * FELEMS, off, 18, acc1, cen0);
    // s1: feeds out0 (K0) and out2 (K6); centers for out1.
    conv2h(sm + 1 * FELEMS, off, 0, acc0, 54, acc2, cen1);
    // f0 -> out0 (K1); retire out0.
    conv1h(sm + 4 * FELEMS, off, 9, acc0, nullptr);
    store8(outp + 0 * CH_STRIDE, cen0, acc0);
    // f1 -> out1 (K3)
    conv1h(sm + 5 * FELEMS, off, 27, acc1, nullptr);
    // s2: feeds out1 (K4) and out3 (K10); centers for out2.
    conv2h(sm + 2 * FELEMS, off, 36, acc1, 90, acc3, cen2);
    // f2 -> out1 (K5); retire out1.
    conv1h(sm + 6 * FELEMS, off, 45, acc1, nullptr);
    store8(outp + 1 * CH_STRIDE, cen1, acc1);
    // f3 -> out2 (K7)
    conv1h(sm + 7 * FELEMS, off, 63, acc2, nullptr);
    // s3: feeds out2 (K8); centers for out3.
    conv1h(sm + 3 * FELEMS, off, 72, acc2, cen3);
    // f4 -> out2 (K9); retire out2.
    conv1h(sm + 8 * FELEMS, off, 81, acc2, nullptr);
    store8(outp + 2 * CH_STRIDE, cen2, acc2);
    // f5 -> out3 (K11); retire out3.
    conv1h(sm + 9 * FELEMS, off, 99, acc3, nullptr);
    store8(outp + 3 * CH_STRIDE, cen3, acc3);
}

extern "C" void kernel_launch(void* const* d_in, const int* in_sizes, int n_in,
                              void* d_out, int out_size) {
    const float* src = (const float*)d_in[0];   // sources (4,32,512,512,1) fp32
    const float* ker = (const float*)d_in[1];   // kernels (12,3,3) fp32
    float* out = (float*)d_out;

    // Weights into constant memory (D2D async copy — graph-capturable memcpy node).
    cudaMemcpyToSymbolAsync(cw, ker, 108 * sizeof(float), 0,
                            cudaMemcpyDeviceToDevice, 0);

    dim3 grid(IMG_W / TW, IMG_H / TH, NBATCH);  // (8, 32, 32)
    fused_bleed<<<grid, 128>>>(src, out);
}

// round 8
// speedup vs baseline: 1.3892x; 1.3892x over previous
#include <cuda_runtime.h>
#include <cuda_fp16.h>

// Problem geometry
#define IMG_H 512
#define IMG_W 512
#define NBATCH 32
#define CH_STRIDE (NBATCH * IMG_H * IMG_W)   // per-channel stride (elements)
#define B_STRIDE  (IMG_H * IMG_W)            // per-batch stride

// Tile geometry: 64 wide x 16 high output tile, +1 halo each side.
#define TW 64
#define TH 16
#define TROWS (TH + 2)      // 18
#define TCOLS (TW + 2)      // 66 valid columns
#define PITCH 68            // row starts 16B-aligned (fp32) / 8B-aligned (fp16)
#define FELEMS (TROWS * PITCH)  // 1224 elements per field
// smem: 4 fp32 source fields + 6 fp16 inter fields = 19584 + 14688 = 34272 B

__constant__ float cw[108];   // 12 3x3 kernels

// cbrt via MUFU lg2/ex2: x >= 0 always here (uniform [0,1) inputs).
// x==0: lg2 -> -inf, ex2(-inf) -> 0. Rel err ~1e-6, fine for 1e-3 gate.
__device__ __forceinline__ float cbrt_fast(float x) {
    float lg;
    asm("lg2.approx.f32 %0, %1;" : "=f"(lg) : "f"(x));
    float e = lg * 0.33333333333333f;
    float r;
    asm("ex2.approx.f32 %0, %1;" : "=f"(r) : "f"(e));
    return r;
}

__device__ __forceinline__ void ldrow_f32(const float* __restrict__ row, float v[6]) {
    float4 a  = *reinterpret_cast<const float4*>(row);      // 16B aligned
    float2 bb = *reinterpret_cast<const float2*>(row + 4);  // 8B aligned
    v[0] = a.x; v[1] = a.y; v[2] = a.z; v[3] = a.w; v[4] = bb.x; v[5] = bb.y;
}

__device__ __forceinline__ void ldrow_f16(const __half* __restrict__ row, float v[6]) {
    const __half2* p = reinterpret_cast<const __half2*>(row);  // 4B aligned (off even)
    float2 a = __half22float2(p[0]);
    float2 b = __half22float2(p[1]);
    float2 c = __half22float2(p[2]);
    v[0] = a.x; v[1] = a.y; v[2] = b.x; v[3] = b.y; v[4] = c.x; v[5] = c.y;
}

// 3x3 conv over a 4-wide x 1-high block; fp32 field. Optionally captures the
// center row (field's own pixels) into cen[4].
__device__ __forceinline__ void conv1(const float* __restrict__ t, int off, int wb,
                                      float acc[4], float* cen) {
    #pragma unroll
    for (int r = 0; r < 3; r++) {
        float v[6];
        ldrow_f32(t + off + r * PITCH, v);
        if (cen && r == 1) { cen[0] = v[1]; cen[1] = v[2]; cen[2] = v[3]; cen[3] = v[4]; }
        #pragma unroll
        for (int ox = 0; ox < 4; ox++) {
            acc[ox] = fmaf(cw[wb + r * 3 + 0], v[ox + 0], acc[ox]);
            acc[ox] = fmaf(cw[wb + r * 3 + 1], v[ox + 1], acc[ox]);
            acc[ox] = fmaf(cw[wb + r * 3 + 2], v[ox + 2], acc[ox]);
        }
    }
}

// Same, fp32 field, two (weight, accumulator) pairs sharing the row loads.
__device__ __forceinline__ void conv2(const float* __restrict__ t, int off,
                                      int wbA, float accA[4],
                                      int wbB, float accB[4], float* cen) {
    #pragma unroll
    for (int r = 0; r < 3; r++) {
        float v[6];
        ldrow_f32(t + off + r * PITCH, v);
        if (cen && r == 1) { cen[0] = v[1]; cen[1] = v[2]; cen[2] = v[3]; cen[3] = v[4]; }
        #pragma unroll
        for (int ox = 0; ox < 4; ox++) {
            accA[ox] = fmaf(cw[wbA + r * 3 + 0], v[ox + 0], accA[ox]);
            accA[ox] = fmaf(cw[wbA + r * 3 + 1], v[ox + 1], accA[ox]);
            accA[ox] = fmaf(cw[wbA + r * 3 + 2], v[ox + 2], accA[ox]);
            accB[ox] = fmaf(cw[wbB + r * 3 + 0], v[ox + 0], accB[ox]);
            accB[ox] = fmaf(cw[wbB + r * 3 + 1], v[ox + 1], accB[ox]);
            accB[ox] = fmaf(cw[wbB + r * 3 + 2], v[ox + 2], accB[ox]);
        }
    }
}

// 3x3 conv, fp16 inter field (fp32 math & accumulate).
__device__ __forceinline__ void conv1h16(const __half* __restrict__ t, int off, int wb,
                                         float acc[4]) {
    #pragma unroll
    for (int r = 0; r < 3; r++) {
        float v[6];
        ldrow_f16(t + off + r * PITCH, v);
        #pragma unroll
        for (int ox = 0; ox < 4; ox++) {
            acc[ox] = fmaf(cw[wb + r * 3 + 0], v[ox + 0], acc[ox]);
            acc[ox] = fmaf(cw[wb + r * 3 + 1], v[ox + 1], acc[ox]);
            acc[ox] = fmaf(cw[wb + r * 3 + 2], v[ox + 2], acc[ox]);
        }
    }
}

__device__ __forceinline__ void store4(float* p, const float cen[4], const float acc[4]) {
    float4 v = { cen[0] - acc[0], cen[1] - acc[1], cen[2] - acc[2], cen[3] - acc[3] };
    *reinterpret_cast<float4*>(p) = v;
}

__global__ __launch_bounds__(256, 5)
void fused_bleed(const float* __restrict__ src, float* __restrict__ out) {
    __shared__ float  sms[4 * FELEMS];            // s0..s3, fp32
    __shared__ __half smf[6 * FELEMS];            // f0..f5, fp16

    const int tid = threadIdx.x;
    const int x0 = blockIdx.x * TW;
    const int y0 = blockIdx.y * TH;
    const int b  = blockIdx.z;

    const float* base = src + b * B_STRIDE;

    // ---- Load halo tiles for all 4 channels; compute the 6 inter fields inline.
    // inter(i,j) = (s_j^0.5 * s_i)^(2/3) = cbrt(s_j) * cbrt(s_i)^2
    for (int idx = tid; idx < TROWS * TCOLS; idx += 256) {
        const int ly = idx / TCOLS;
        const int lx = idx - ly * TCOLS;
        const int gy = y0 - 1 + ly;
        const int gx = x0 - 1 + lx;
        float s0 = 0.f, s1 = 0.f, s2 = 0.f, s3 = 0.f;
        if ((unsigned)gy < (unsigned)IMG_H && (unsigned)gx < (unsigned)IMG_W) {
            const int g = gy * IMG_W + gx;
            s0 = base[g];
            s1 = base[g + CH_STRIDE];
            s2 = base[g + 2 * CH_STRIDE];
            s3 = base[g + 3 * CH_STRIDE];
        }
        const int o = ly * PITCH + lx;
        sms[o]              = s0;
        sms[o + FELEMS]     = s1;
        sms[o + 2 * FELEMS] = s2;
        sms[o + 3 * FELEMS] = s3;
        const float c0 = cbrt_fast(s0), c1 = cbrt_fast(s1);
        const float c2 = cbrt_fast(s2), c3 = cbrt_fast(s3);
        const float q0 = c0 * c0, q1 = c1 * c1, q2 = c2 * c2, q3 = c3 * c3;
        smf[o]              = __float2half_rn(c1 * q0);   // f0: (0,1) -> K1
        smf[o + FELEMS]     = __float2half_rn(c0 * q1);   // f1: (1,0) -> K3
        smf[o + 2 * FELEMS] = __float2half_rn(c2 * q1);   // f2: (1,2) -> K5
        smf[o + 3 * FELEMS] = __float2half_rn(c1 * q2);   // f3: (2,1) -> K7
        smf[o + 4 * FELEMS] = __float2half_rn(c3 * q2);   // f4: (2,3) -> K9
        smf[o + 5 * FELEMS] = __float2half_rn(c2 * q3);   // f5: (3,2) -> K11
    }
    __syncthreads();

    // ---- Compute phase: each thread owns a 4-wide x 1-high block, all 4 channels.
    const int tx = tid & 15;
    const int ty = tid >> 4;
    const int off = ty * PITCH + tx * 4;   // window top-left (even -> half2-aligned)
    float* outp = out + b * B_STRIDE + (y0 + ty) * IMG_W + (x0 + tx * 4);

    float acc0[4] = {}, acc1[4] = {}, acc2[4] = {}, acc3[4] = {};
    float cen0[4], cen1[4], cen2[4], cen3[4];

    // s0: feeds out1 (K2); centers for out0.
    conv1(sms + 0 * FELEMS, off, 18, acc1, cen0);
    // s1: feeds out0 (K0) and out2 (K6); centers for out1.
    conv2(sms + 1 * FELEMS, off, 0, acc0, 54, acc2, cen1);
    // f0 -> out0 (K1); retire out0.
    conv1h16(smf + 0 * FELEMS, off, 9, acc0);
    store4(outp + 0 * CH_STRIDE, cen0, acc0);
    // f1 -> out1 (K3)
    conv1h16(smf + 1 * FELEMS, off, 27, acc1);
    // s2: feeds out1 (K4) and out3 (K10); centers for out2.
    conv2(sms + 2 * FELEMS, off, 36, acc1, 90, acc3, cen2);
    // f2 -> out1 (K5); retire out1.
    conv1h16(smf + 2 * FELEMS, off, 45, acc1);
    store4(outp + 1 * CH_STRIDE, cen1, acc1);
    // f3 -> out2 (K7)
    conv1h16(smf + 3 * FELEMS, off, 63, acc2);
    // s3: feeds out2 (K8); centers for out3.
    conv1(sms + 3 * FELEMS, off, 72, acc2, cen3);
    // f4 -> out2 (K9); retire out2.
    conv1h16(smf + 4 * FELEMS, off, 81, acc2);
    store4(outp + 2 * CH_STRIDE, cen2, acc2);
    // f5 -> out3 (K11); retire out3.
    conv1h16(smf + 5 * FELEMS, off, 99, acc3);
    store4(outp + 3 * CH_STRIDE, cen3, acc3);
}

extern "C" void kernel_launch(void* const* d_in, const int* in_sizes, int n_in,
                              void* d_out, int out_size) {
    const float* src = (const float*)d_in[0];   // sources (4,32,512,512,1) fp32
    const float* ker = (const float*)d_in[1];   // kernels (12,3,3) fp32
    float* out = (float*)d_out;

    // Weights into constant memory (D2D async copy — graph-capturable memcpy node).
    cudaMemcpyToSymbolAsync(cw, ker, 108 * sizeof(float), 0,
                            cudaMemcpyDeviceToDevice, 0);

    dim3 grid(IMG_W / TW, IMG_H / TH, NBATCH);  // (8, 32, 32)
    fused_bleed<<<grid, 256>>>(src, out);
}